// round 2
// baseline (speedup 1.0000x reference)
#include <cuda_runtime.h>
#include <cuda_bf16.h>

// Problem constants
#define Tn   4096
#define Bn   64
#define Hn   256
#define G4   1024   // 4*H
#define INC  16
#define OUTC 20

#define NBLK 128    // 16 hidden-groups x 8 batch-groups
#define NTHR 128

// ---------------- scratch (device globals; no allocations allowed) -------
__device__ float g_h1[(size_t)Tn * Bn * Hn];   // layer1 hidden states, 256 MB
__device__ float g_h2[(size_t)Tn * Bn * Hn];   // layer2 hidden states, 256 MB
__device__ unsigned g_sync[4];                 // {cnt1, epoch1, cnt2, epoch2}

// ---------------- grid barrier (all 128 blocks resident) -----------------
__device__ __forceinline__ void grid_barrier(unsigned* cnt, volatile unsigned* ep,
                                             unsigned e_next) {
    __syncthreads();
    if (threadIdx.x == 0) {
        __threadfence();                              // release my h writes
        unsigned prev = atomicAdd(cnt, 1u);
        if (prev == (unsigned)gridDim.x - 1u) {
            atomicExch(cnt, 0u);
            __threadfence();
            *ep = e_next;                             // release everyone
        } else {
            while (*ep < e_next) { }                  // spin on L2
            __threadfence();                          // acquire
        }
    }
    __syncthreads();
}

// Map local gate column c (0..63) -> global gate row (gate-quadrant major)
__device__ __forceinline__ int gate_row(int c, int j0) {
    return ((c >> 4) << 8) + j0 + (c & 15);           // q*256 + (j0 + j)
}

// 8-k inner-product step macro: 2 batches x 2 adjacent columns
#define FMA2x2(hA, hB, OFF)                                         \
    { float2 w = *(const float2*)(wp + (OFF) * 66);                 \
      a00 += (hA) * w.x; a01 += (hA) * w.y;                         \
      a10 += (hB) * w.x; a11 += (hB) * w.y; }

// =========================== Layer 1 =====================================
// SMEM floats: Wh[256][66] | Wi[16][66] | bs[64] | hs[8][256] | xs[8][16]
//            | gs[8][64]   | cs[8][16]
#define L1_SMEM_F (256*66 + 16*66 + 64 + 8*256 + 8*16 + 8*64 + 8*16)

__global__ void lstm_layer1(const float* __restrict__ x,
                            const float* __restrict__ Wih,
                            const float* __restrict__ Whh,
                            const float* __restrict__ bih,
                            const float* __restrict__ bhh) {
    extern __shared__ float sm[];
    float* Wh = sm;                      // [256][66] transposed Whh slice
    float* Wi = Wh + 256 * 66;           // [16][66]  transposed Wih slice
    float* bs = Wi + 16 * 66;            // [64]
    float* hs = bs + 64;                 // [8][256]
    float* xs = hs + 8 * 256;            // [8][16]
    float* gs = xs + 8 * 16;             // [8][64]
    float* cs = gs + 8 * 64;             // [8][16]

    const int tid = threadIdx.x;
    const int jj  = blockIdx.x & 15;     // hidden group (16 units)
    const int bb  = blockIdx.x >> 4;     // batch group (8 rows)
    const int j0  = jj * 16;
    const int b0  = bb * 8;

    // Load weights transposed into SMEM (one time)
    for (int idx = tid; idx < 64 * 256; idx += NTHR) {
        int c = idx >> 8, k = idx & 255;
        Wh[k * 66 + c] = Whh[gate_row(c, j0) * Hn + k];
    }
    for (int idx = tid; idx < 64 * 16; idx += NTHR) {
        int c = idx >> 4, k = idx & 15;
        Wi[k * 66 + c] = Wih[gate_row(c, j0) * INC + k];
    }
    if (tid < 64) {
        int r = gate_row(tid, j0);
        bs[tid] = bih[r] + bhh[r];
    }
    cs[tid] = 0.f;                       // 128 entries == NTHR
    __syncthreads();

    const int lane = tid & 31;
    const int wrp  = tid >> 5;           // 0..3
    const int bA   = 2 * wrp;
    const int bB   = 2 * wrp + 1;
    const int c0   = 2 * lane;           // columns c0, c0+1

    for (int t = 0; t < Tn; ++t) {
        // stage previous h (or zeros) and x_t
        if (t == 0) {
            float4 z = make_float4(0.f, 0.f, 0.f, 0.f);
            for (int i = tid; i < 512; i += NTHR)
                ((float4*)hs)[i] = z;
        } else {
            const float4* hp =
                (const float4*)(g_h1 + ((size_t)(t - 1) * Bn + b0) * Hn);
            for (int i = tid; i < 512; i += NTHR)
                ((float4*)hs)[i] = hp[i];
        }
        {
            int b = tid >> 4, d = tid & 15;
            xs[tid] = x[(size_t)(b0 + b) * INC * Tn + (size_t)d * Tn + t];
        }
        __syncthreads();

        float a00 = bs[c0], a01 = bs[c0 + 1];
        float a10 = a00,    a11 = a01;

        // input contribution (K = 16)
        const float* xA = xs + bA * 16;
        const float* xB = xs + bB * 16;
        {
            const float* wp = Wi + c0;
            #pragma unroll
            for (int k = 0; k < 16; ++k) {
                float2 w = *(const float2*)(wp + k * 66);
                a00 += xA[k] * w.x; a01 += xA[k] * w.y;
                a10 += xB[k] * w.x; a11 += xB[k] * w.y;
            }
        }
        // recurrent contribution (K = 256)
        {
            const float* hA = hs + bA * 256;
            const float* hB = hs + bB * 256;
            #pragma unroll 4
            for (int k0 = 0; k0 < 256; k0 += 8) {
                float4 A0 = *(const float4*)(hA + k0);
                float4 A1 = *(const float4*)(hA + k0 + 4);
                float4 B0 = *(const float4*)(hB + k0);
                float4 B1 = *(const float4*)(hB + k0 + 4);
                const float* wp = Wh + (size_t)k0 * 66 + c0;
                FMA2x2(A0.x, B0.x, 0) FMA2x2(A0.y, B0.y, 1)
                FMA2x2(A0.z, B0.z, 2) FMA2x2(A0.w, B0.w, 3)
                FMA2x2(A1.x, B1.x, 4) FMA2x2(A1.y, B1.y, 5)
                FMA2x2(A1.z, B1.z, 6) FMA2x2(A1.w, B1.w, 7)
            }
        }
        gs[bA * 64 + c0] = a00; gs[bA * 64 + c0 + 1] = a01;
        gs[bB * 64 + c0] = a10; gs[bB * 64 + c0 + 1] = a11;
        __syncthreads();

        // elementwise update: thread u -> (batch u>>4, hidden u&15)
        {
            int b = tid >> 4, j = tid & 15;
            float gi = gs[b * 64 + j];
            float gf = gs[b * 64 + 16 + j];
            float gg = gs[b * 64 + 32 + j];
            float go = gs[b * 64 + 48 + j];
            gi = 1.f / (1.f + __expf(-gi));
            gf = 1.f / (1.f + __expf(-gf));
            gg = tanhf(gg);
            go = 1.f / (1.f + __expf(-go));
            float c = gf * cs[tid] + gi * gg;
            cs[tid] = c;
            float h = go * tanhf(c);
            g_h1[((size_t)t * Bn + b0 + b) * Hn + j0 + j] = h;
        }
        grid_barrier(&g_sync[0], &g_sync[1], (unsigned)(t + 1));
    }
}

// =========================== Layer 2 =====================================
// SMEM floats: Wi[256][66] | Wh[256][66] | bs[64] | hin[8][256]
//            | hrec[8][256] | gs[8][64] | cs[8][16]
#define L2_SMEM_F (2*256*66 + 64 + 2*8*256 + 8*64 + 8*16)

__global__ void lstm_layer2(const float* __restrict__ Wih,
                            const float* __restrict__ Whh,
                            const float* __restrict__ bih,
                            const float* __restrict__ bhh) {
    extern __shared__ float sm[];
    float* Wi   = sm;                    // [256][66]
    float* Wh   = Wi + 256 * 66;         // [256][66]
    float* bs   = Wh + 256 * 66;         // [64]
    float* hin  = bs + 64;               // [8][256]  layer1 h at t
    float* hrec = hin + 8 * 256;         // [8][256]  layer2 h at t-1
    float* gs   = hrec + 8 * 256;        // [8][64]
    float* cs   = gs + 8 * 64;           // [8][16]

    const int tid = threadIdx.x;
    const int jj  = blockIdx.x & 15;
    const int bb  = blockIdx.x >> 4;
    const int j0  = jj * 16;
    const int b0  = bb * 8;

    for (int idx = tid; idx < 64 * 256; idx += NTHR) {
        int c = idx >> 8, k = idx & 255;
        int r = gate_row(c, j0);
        Wi[k * 66 + c] = Wih[r * Hn + k];
        Wh[k * 66 + c] = Whh[r * Hn + k];
    }
    if (tid < 64) {
        int r = gate_row(tid, j0);
        bs[tid] = bih[r] + bhh[r];
    }
    cs[tid] = 0.f;
    __syncthreads();

    const int lane = tid & 31;
    const int wrp  = tid >> 5;
    const int bA   = 2 * wrp;
    const int bB   = 2 * wrp + 1;
    const int c0   = 2 * lane;

    for (int t = 0; t < Tn; ++t) {
        {
            const float4* ip =
                (const float4*)(g_h1 + ((size_t)t * Bn + b0) * Hn);
            for (int i = tid; i < 512; i += NTHR)
                ((float4*)hin)[i] = ip[i];
        }
        if (t == 0) {
            float4 z = make_float4(0.f, 0.f, 0.f, 0.f);
            for (int i = tid; i < 512; i += NTHR)
                ((float4*)hrec)[i] = z;
        } else {
            const float4* rp =
                (const float4*)(g_h2 + ((size_t)(t - 1) * Bn + b0) * Hn);
            for (int i = tid; i < 512; i += NTHR)
                ((float4*)hrec)[i] = rp[i];
        }
        __syncthreads();

        float a00 = bs[c0], a01 = bs[c0 + 1];
        float a10 = a00,    a11 = a01;

        // input GEMV (K=256) with Wi / hin
        {
            const float* hA = hin + bA * 256;
            const float* hB = hin + bB * 256;
            #pragma unroll 4
            for (int k0 = 0; k0 < 256; k0 += 8) {
                float4 A0 = *(const float4*)(hA + k0);
                float4 A1 = *(const float4*)(hA + k0 + 4);
                float4 B0 = *(const float4*)(hB + k0);
                float4 B1 = *(const float4*)(hB + k0 + 4);
                const float* wp = Wi + (size_t)k0 * 66 + c0;
                FMA2x2(A0.x, B0.x, 0) FMA2x2(A0.y, B0.y, 1)
                FMA2x2(A0.z, B0.z, 2) FMA2x2(A0.w, B0.w, 3)
                FMA2x2(A1.x, B1.x, 4) FMA2x2(A1.y, B1.y, 5)
                FMA2x2(A1.z, B1.z, 6) FMA2x2(A1.w, B1.w, 7)
            }
        }
        // recurrent GEMV (K=256) with Wh / hrec
        {
            const float* hA = hrec + bA * 256;
            const float* hB = hrec + bB * 256;
            #pragma unroll 4
            for (int k0 = 0; k0 < 256; k0 += 8) {
                float4 A0 = *(const float4*)(hA + k0);
                float4 A1 = *(const float4*)(hA + k0 + 4);
                float4 B0 = *(const float4*)(hB + k0);
                float4 B1 = *(const float4*)(hB + k0 + 4);
                const float* wp = Wh + (size_t)k0 * 66 + c0;
                FMA2x2(A0.x, B0.x, 0) FMA2x2(A0.y, B0.y, 1)
                FMA2x2(A0.z, B0.z, 2) FMA2x2(A0.w, B0.w, 3)
                FMA2x2(A1.x, B1.x, 4) FMA2x2(A1.y, B1.y, 5)
                FMA2x2(A1.z, B1.z, 6) FMA2x2(A1.w, B1.w, 7)
            }
        }
        gs[bA * 64 + c0] = a00; gs[bA * 64 + c0 + 1] = a01;
        gs[bB * 64 + c0] = a10; gs[bB * 64 + c0 + 1] = a11;
        __syncthreads();

        {
            int b = tid >> 4, j = tid & 15;
            float gi = gs[b * 64 + j];
            float gf = gs[b * 64 + 16 + j];
            float gg = gs[b * 64 + 32 + j];
            float go = gs[b * 64 + 48 + j];
            gi = 1.f / (1.f + __expf(-gi));
            gf = 1.f / (1.f + __expf(-gf));
            gg = tanhf(gg);
            go = 1.f / (1.f + __expf(-go));
            float c = gf * cs[tid] + gi * gg;
            cs[tid] = c;
            float h = go * tanhf(c);
            g_h2[((size_t)t * Bn + b0 + b) * Hn + j0 + j] = h;
        }
        grid_barrier(&g_sync[2], &g_sync[3], (unsigned)(t + 1));
    }
}

// =========================== Head ========================================
// grid (T/64, B); block 256 threads.
// SMEM: Wt[256][20] (transposed Whead) | A[64][256] (leaky h2 tile)
#define HD_SMEM_F (256*20 + 64*256)

__global__ void head_kernel(const float* __restrict__ Whead,
                            const float* __restrict__ bhead,
                            float* __restrict__ out) {
    extern __shared__ float sm[];
    float* Wt = sm;                  // [256][20]
    float* A  = Wt + 256 * 20;       // [64][256]

    const int tid = threadIdx.x;
    const int t0  = blockIdx.x * 64;
    const int b   = blockIdx.y;

    for (int idx = tid; idx < 256 * 20; idx += 256) {
        int k = idx / 20, o = idx % 20;
        Wt[idx] = Whead[o * Hn + k];
    }
    for (int idx = tid; idx < 64 * 256; idx += 256) {
        int tt = idx >> 8, k = idx & 255;
        float v = g_h2[((size_t)(t0 + tt) * Bn + b) * Hn + k];
        A[idx] = v >= 0.f ? v : 0.01f * v;
    }
    __syncthreads();

    for (int idx = tid; idx < 64 * 20; idx += 256) {
        int tt = idx / 20, o = idx % 20;
        float acc = bhead[o];
        const float* a = A + tt * 256;
        #pragma unroll 8
        for (int k = 0; k < 256; ++k)
            acc += a[k] * Wt[k * 20 + o];
        out[(size_t)b * OUTC * Tn + (size_t)o * Tn + t0 + tt] = acc;
    }
}

// =========================== launch ======================================
extern "C" void kernel_launch(void* const* d_in, const int* in_sizes, int n_in,
                              void* d_out, int out_size) {
    const float* x     = (const float*)d_in[0];
    const float* Wih0  = (const float*)d_in[1];
    const float* Whh0  = (const float*)d_in[2];
    const float* bih0  = (const float*)d_in[3];
    const float* bhh0  = (const float*)d_in[4];
    const float* Wih1  = (const float*)d_in[5];
    const float* Whh1  = (const float*)d_in[6];
    const float* bih1  = (const float*)d_in[7];
    const float* bhh1  = (const float*)d_in[8];
    const float* Whead = (const float*)d_in[9];
    const float* bhead = (const float*)d_in[10];
    float* out = (float*)d_out;

    const size_t s1 = (size_t)L1_SMEM_F * sizeof(float);   //  ~83 KB
    const size_t s2 = (size_t)L2_SMEM_F * sizeof(float);   // ~154 KB
    const size_t sh = (size_t)HD_SMEM_F * sizeof(float);   //  ~84 KB
    cudaFuncSetAttribute(lstm_layer1, cudaFuncAttributeMaxDynamicSharedMemorySize, (int)s1);
    cudaFuncSetAttribute(lstm_layer2, cudaFuncAttributeMaxDynamicSharedMemorySize, (int)s2);
    cudaFuncSetAttribute(head_kernel, cudaFuncAttributeMaxDynamicSharedMemorySize, (int)sh);

    // reset grid-barrier state (deterministic across graph replays)
    void* syncp = nullptr;
    cudaGetSymbolAddress(&syncp, g_sync);
    cudaMemsetAsync(syncp, 0, 4 * sizeof(unsigned), 0);

    lstm_layer1<<<NBLK, NTHR, s1>>>(x, Wih0, Whh0, bih0, bhh0);
    lstm_layer2<<<NBLK, NTHR, s2>>>(Wih1, Whh1, bih1, bhh1);
    head_kernel<<<dim3(Tn / 64, Bn), 256, sh>>>(Whead, bhead, out);
}